// round 6
// baseline (speedup 1.0000x reference)
#include <cuda_runtime.h>
#include <math.h>
#include <stdint.h>

#define SQ   2048
#define DIM  1024
#define NH   16
#define HD   64
#define DFF  4096
#define NE   8
#define EPSV 1.1920928955078125e-07f
#define NEG_INF (__int_as_float(0xff800000))

// ------------------------- scratch (device globals) -------------------------
__device__ float g_h   [(size_t)SQ*DIM];
__device__ float g_qkv [(size_t)SQ*3*DIM];
__device__ float g_o   [(size_t)SQ*DIM];
__device__ float g_x2  [(size_t)SQ*DIM];
__device__ float g_h2  [(size_t)SQ*DIM];
__device__ float g_probs[(size_t)SQ*NE];
__device__ float g_topw [(size_t)SQ*2];
__device__ int   g_cnt  [NE];
__device__ int   g_atok [(size_t)NE*SQ];
__device__ int   g_aslot[(size_t)NE*SQ];
__device__ float g_hid  [(size_t)NE*SQ*DFF];   // 256 MB bss scratch
__device__ float g_y    [(size_t)SQ*2*DIM];

// ------------------------- helpers -------------------------
__device__ __forceinline__ uint32_t f2tf32(float x) {
    uint32_t r;
    asm("cvt.rna.tf32.f32 %0, %1;" : "=r"(r) : "f"(x));
    return r;
}

// float4 accumulator, scalar operands — nothing address-taken, no local memory.
__device__ __forceinline__ void mma4(float4& c,
                                     uint32_t a0, uint32_t a1, uint32_t a2, uint32_t a3,
                                     uint32_t b0, uint32_t b1) {
    asm volatile(
        "mma.sync.aligned.m16n8k8.row.col.f32.tf32.tf32.f32 "
        "{%0,%1,%2,%3}, {%4,%5,%6,%7}, {%8,%9}, {%0,%1,%2,%3};"
        : "+f"(c.x), "+f"(c.y), "+f"(c.z), "+f"(c.w)
        : "r"(a0), "r"(a1), "r"(a2), "r"(a3), "r"(b0), "r"(b1));
}

__device__ __forceinline__ void cp_async16(uint32_t saddr, const void* gptr, int srcsz) {
    asm volatile("cp.async.ca.shared.global [%0], [%1], 16, %2;"
                 :: "r"(saddr), "l"(gptr), "r"(srcsz) : "memory");
}
__device__ __forceinline__ void cp_commit() { asm volatile("cp.async.commit_group;" ::: "memory"); }
__device__ __forceinline__ void cp_wait0()  { asm volatile("cp.async.wait_group 0;" ::: "memory"); }

// ------------------------- small kernels -------------------------
__global__ void zero_cnt_kernel() {
    if (threadIdx.x < NE) g_cnt[threadIdx.x] = 0;
}

__global__ void __launch_bounds__(256) rmsnorm_kernel(const float* __restrict__ xin,
                                                      const float* __restrict__ w, int which) {
    const float* src = which ? g_x2 : xin;
    float* dst = which ? g_h2 : g_h;
    int t = blockIdx.x;
    const float* xr = src + (size_t)t * DIM;
    float s = 0.f;
    for (int i = threadIdx.x; i < DIM; i += 256) { float v = xr[i]; s += v * v; }
    __shared__ float red[8];
    for (int o = 16; o; o >>= 1) s += __shfl_xor_sync(0xffffffffu, s, o);
    if ((threadIdx.x & 31) == 0) red[threadIdx.x >> 5] = s;
    __syncthreads();
    if (threadIdx.x == 0) {
        float v = 0.f;
        #pragma unroll
        for (int i = 0; i < 8; i++) v += red[i];
        red[0] = v;
    }
    __syncthreads();
    float rs = rsqrtf(red[0] * (1.f / DIM) + EPSV);
    float* dr = dst + (size_t)t * DIM;
    for (int i = threadIdx.x; i < DIM; i += 256) dr[i] = xr[i] * rs * w[i];
}

__global__ void __launch_bounds__(256) rope_kernel() {
    int t = blockIdx.x;
    for (int it = threadIdx.x; it < 1024; it += 256) {
        int which = it >> 9;
        int rem = it & 511;
        int hh = rem >> 5, j = rem & 31;
        float inv = expf(-0.28782313662425575f * (float)j);
        float ang = (float)t * inv;
        float sn, cs;
        sincosf(ang, &sn, &cs);
        float* p = g_qkv + (size_t)t * 3072 + which * 1024 + hh * 64;
        float x1 = p[j], x2 = p[j + 32];
        p[j]      = x1 * cs - x2 * sn;
        p[j + 32] = x2 * cs + x1 * sn;
    }
}

// ------------------------- tf32 tensor-core GEMM -------------------------
// C[M,N] = A[M,K]*B[N,K]^T. 128x128 tile, BK=16, 512 threads (4x4 warps, 32x32 warp tile).
// PREC=1: 3xTF32 (hi/lo split) for full-accuracy (QKV / out-proj feed the router decision).
// All accumulators/fragments are named scalars/float4 — zero local memory by construction.
#define BROW 20

#define LOADB(J) \
    float fb##J##0 = bs[(wn * 32 + 8 * J + g) * BROW + kk + t]; \
    float fb##J##1 = bs[(wn * 32 + 8 * J + g) * BROW + kk + t + 4];

#define CVTB(J) \
    uint32_t hb##J##0 = f2tf32(fb##J##0); \
    uint32_t hb##J##1 = f2tf32(fb##J##1);

#define SPLB(J) \
    uint32_t hb##J##0 = f2tf32(fb##J##0); \
    uint32_t lb##J##0 = f2tf32(fb##J##0 - __uint_as_float(hb##J##0)); \
    uint32_t hb##J##1 = f2tf32(fb##J##1); \
    uint32_t lb##J##1 = f2tf32(fb##J##1 - __uint_as_float(hb##J##1));

#define DOROW(TI) { \
    int rb = (wm * 32 + TI * 16 + g) * BROW + kk + t; \
    uint32_t ha0 = f2tf32(as[rb]); \
    uint32_t ha1 = f2tf32(as[rb + 8 * BROW]); \
    uint32_t ha2 = f2tf32(as[rb + 4]); \
    uint32_t ha3 = f2tf32(as[rb + 8 * BROW + 4]); \
    mma4(c##TI##0, ha0, ha1, ha2, ha3, hb00, hb01); \
    mma4(c##TI##1, ha0, ha1, ha2, ha3, hb10, hb11); \
    mma4(c##TI##2, ha0, ha1, ha2, ha3, hb20, hb21); \
    mma4(c##TI##3, ha0, ha1, ha2, ha3, hb30, hb31); }

#define DOROW_P(TI) { \
    int rb = (wm * 32 + TI * 16 + g) * BROW + kk + t; \
    float fa0 = as[rb]; \
    float fa1 = as[rb + 8 * BROW]; \
    float fa2 = as[rb + 4]; \
    float fa3 = as[rb + 8 * BROW + 4]; \
    uint32_t ha0 = f2tf32(fa0), ha1 = f2tf32(fa1), ha2 = f2tf32(fa2), ha3 = f2tf32(fa3); \
    uint32_t la0 = f2tf32(fa0 - __uint_as_float(ha0)); \
    uint32_t la1 = f2tf32(fa1 - __uint_as_float(ha1)); \
    uint32_t la2 = f2tf32(fa2 - __uint_as_float(ha2)); \
    uint32_t la3 = f2tf32(fa3 - __uint_as_float(ha3)); \
    mma4(c##TI##0, la0, la1, la2, la3, hb00, hb01); \
    mma4(c##TI##0, ha0, ha1, ha2, ha3, lb00, lb01); \
    mma4(c##TI##0, ha0, ha1, ha2, ha3, hb00, hb01); \
    mma4(c##TI##1, la0, la1, la2, la3, hb10, hb11); \
    mma4(c##TI##1, ha0, ha1, ha2, ha3, lb10, lb11); \
    mma4(c##TI##1, ha0, ha1, ha2, ha3, hb10, hb11); \
    mma4(c##TI##2, la0, la1, la2, la3, hb20, hb21); \
    mma4(c##TI##2, ha0, ha1, ha2, ha3, lb20, lb21); \
    mma4(c##TI##2, ha0, ha1, ha2, ha3, hb20, hb21); \
    mma4(c##TI##3, la0, la1, la2, la3, hb30, hb31); \
    mma4(c##TI##3, ha0, ha1, ha2, ha3, lb30, lb31); \
    mma4(c##TI##3, ha0, ha1, ha2, ha3, hb30, hb31); }

#define EPI1(CT, J) do { \
    int col = n0 + wn * 32 + 8 * J + 2 * t; \
    float v0 = rh ? (CT).z : (CT).x; \
    float v1 = rh ? (CT).w : (CT).y; \
    if (MODE == 0) { \
        *(float2*)(g_qkv + (size_t)r * 3072 + col) = make_float2(v0, v1); \
    } else if (MODE == 1) { \
        size_t off = (size_t)r * DIM + col; \
        g_x2[off]     = xres[off]     + v0; \
        g_x2[off + 1] = xres[off + 1] + v1; \
    } else if (MODE == 2) { \
        float gl0 = 0.5f * v0 * (1.f + erff(v0 * 0.7071067811865476f)); \
        float gl1 = 0.5f * v1 * (1.f + erff(v1 * 0.7071067811865476f)); \
        *(float2*)(g_hid + (size_t)e * SQ * DFF + (size_t)r * DFF + col) = make_float2(gl0, gl1); \
    } else { \
        *(float2*)(g_y + ((size_t)tok * 2 + slot) * DIM + col) = make_float2(v0 * wt, v1 * wt); \
    } \
} while (0)

template<int MODE, int PREC>
__global__ void __launch_bounds__(512) tc_gemm(const float* __restrict__ W,
                                               const float* __restrict__ xres,
                                               int Kdim) {
    __shared__ float As[2][128 * BROW];
    __shared__ float Bs[2][128 * BROW];

    int m0 = blockIdx.x * 128, n0 = blockIdx.y * 128;
    int e = (MODE >= 2) ? blockIdx.z : 0;
    int Mv = (MODE >= 2) ? g_cnt[e] : SQ;
    if (MODE >= 2 && m0 >= Mv) return;

    const float* A;
    const float* B;
    if (MODE == 0)      { A = g_h;                          B = W; }
    else if (MODE == 1) { A = g_o;                          B = W; }
    else if (MODE == 2) { A = g_h2;                         B = W + (size_t)e * DFF * DIM; }
    else                { A = g_hid + (size_t)e * SQ * DFF; B = W + (size_t)e * DIM * DFF; }

    int tid = threadIdx.x;
    int lr = tid >> 2, kq = tid & 3;

    const float* arow;
    int apred = 16;
    if (MODE == 2) {
        int r = m0 + lr;
        bool valid = r < Mv;
        apred = valid ? 16 : 0;
        int row = valid ? g_atok[(size_t)e * SQ + r] : 0;
        arow = A + (size_t)row * Kdim + kq * 4;
    } else {
        arow = A + (size_t)(m0 + lr) * Kdim + kq * 4;
    }
    const float* brow = B + (size_t)(n0 + lr) * Kdim + kq * 4;

    uint32_t a_s = (uint32_t)__cvta_generic_to_shared(&As[0][lr * BROW + kq * 4]);
    uint32_t b_s = (uint32_t)__cvta_generic_to_shared(&Bs[0][lr * BROW + kq * 4]);
    const uint32_t bufoff = 128 * BROW * 4;

#define LOADG(BUF, K0)                                            \
    do {                                                          \
        cp_async16(a_s + (BUF) * bufoff, arow + (K0), apred);     \
        cp_async16(b_s + (BUF) * bufoff, brow + (K0), 16);        \
        cp_commit();                                              \
    } while (0)

    int warp = tid >> 5, lane = tid & 31;
    int wm = warp >> 2, wn = warp & 3;
    int g = lane >> 2, t = lane & 3;

    float4 c00 = make_float4(0.f, 0.f, 0.f, 0.f);
    float4 c01 = c00, c02 = c00, c03 = c00;
    float4 c10 = c00, c11 = c00, c12 = c00, c13 = c00;

    int nIter = Kdim >> 4;
    LOADG(0, 0);

    for (int it = 0; it < nIter; ++it) {
        cp_wait0();
        __syncthreads();
        int nxt = it + 1;
        if (nxt < nIter) LOADG(nxt & 1, nxt << 4);

        const float* as = As[it & 1];
        const float* bs = Bs[it & 1];
        #pragma unroll
        for (int kh = 0; kh < 2; kh++) {
            int kk = kh * 8;
            LOADB(0) LOADB(1) LOADB(2) LOADB(3)
            if (PREC) {
                SPLB(0) SPLB(1) SPLB(2) SPLB(3)
                DOROW_P(0)
                DOROW_P(1)
            } else {
                CVTB(0) CVTB(1) CVTB(2) CVTB(3)
                DOROW(0)
                DOROW(1)
            }
        }
        __syncthreads();
    }

    // ---------------- epilogue ----------------
    for (int rh = 0; rh < 2; rh++) {
        {
            int r = m0 + wm * 32 + g + rh * 8;
            if (!(MODE >= 2 && r >= Mv)) {
                int tok = 0, slot = 0; float wt = 0.f;
                if (MODE == 3) {
                    tok  = g_atok [(size_t)e * SQ + r];
                    slot = g_aslot[(size_t)e * SQ + r];
                    wt   = g_topw[tok * 2 + slot];
                }
                EPI1(c00, 0); EPI1(c01, 1); EPI1(c02, 2); EPI1(c03, 3);
            }
        }
        {
            int r = m0 + wm * 32 + 16 + g + rh * 8;
            if (!(MODE >= 2 && r >= Mv)) {
                int tok = 0, slot = 0; float wt = 0.f;
                if (MODE == 3) {
                    tok  = g_atok [(size_t)e * SQ + r];
                    slot = g_aslot[(size_t)e * SQ + r];
                    wt   = g_topw[tok * 2 + slot];
                }
                EPI1(c10, 0); EPI1(c11, 1); EPI1(c12, 2); EPI1(c13, 3);
            }
        }
    }
#undef LOADG
}

// ------------------------- attention (flash, fp32) -------------------------
__global__ void __launch_bounds__(256) attn_kernel() {
    extern __shared__ float sm[];
    float* Qs = sm;              // [64][65]
    float* KP = sm + 64 * 65;    // [64][65]
    float* Vs = KP + 64 * 65;    // [64][64]
    int h  = blockIdx.y;
    int q0 = blockIdx.x * 64;
    int tid = threadIdx.x, tx = tid & 15, ty = tid >> 4;

    for (int idx = tid; idx < 64 * 16; idx += 256) {
        int r = idx >> 4, d4 = idx & 15;
        float4 v = *(const float4*)(g_qkv + (size_t)(q0 + r) * 3072 + h * 64 + d4 * 4);
        float* q = Qs + r * 65 + d4 * 4;
        q[0] = v.x * 0.125f; q[1] = v.y * 0.125f; q[2] = v.z * 0.125f; q[3] = v.w * 0.125f;
    }

    float m[4], l[4], O[4][4];
    #pragma unroll
    for (int i = 0; i < 4; i++) {
        m[i] = NEG_INF; l[i] = 0.f;
        #pragma unroll
        for (int j = 0; j < 4; j++) O[i][j] = 0.f;
    }

    int nk = blockIdx.x;
    for (int kt = 0; kt <= nk; kt++) {
        int k0 = kt * 64;
        __syncthreads();
        for (int idx = tid; idx < 64 * 16; idx += 256) {
            int r = idx >> 4, d4 = idx & 15;
            const float* kb = g_qkv + (size_t)(k0 + r) * 3072 + 1024 + h * 64 + d4 * 4;
            float4 kv = *(const float4*)kb;
            float* kp = KP + r * 65 + d4 * 4;
            kp[0] = kv.x; kp[1] = kv.y; kp[2] = kv.z; kp[3] = kv.w;
            float4 vv = *(const float4*)(kb + 1024);
            *(float4*)(Vs + r * 64 + d4 * 4) = vv;
        }
        __syncthreads();

        float sacc[4][4];
        #pragma unroll
        for (int i = 0; i < 4; i++)
            #pragma unroll
            for (int j = 0; j < 4; j++) sacc[i][j] = 0.f;
        for (int d = 0; d < 64; d++) {
            float a[4], b[4];
            #pragma unroll
            for (int i = 0; i < 4; i++) a[i] = Qs[(4 * ty + i) * 65 + d];
            #pragma unroll
            for (int j = 0; j < 4; j++) b[j] = KP[(4 * tx + j) * 65 + d];
            #pragma unroll
            for (int i = 0; i < 4; i++)
                #pragma unroll
                for (int j = 0; j < 4; j++) sacc[i][j] = fmaf(a[i], b[j], sacc[i][j]);
        }
        if (kt == nk) {
            #pragma unroll
            for (int i = 0; i < 4; i++)
                #pragma unroll
                for (int j = 0; j < 4; j++)
                    if (4 * tx + j > 4 * ty + i) sacc[i][j] = NEG_INF;
        }

        float pl[4][4];
        #pragma unroll
        for (int i = 0; i < 4; i++) {
            float mm = sacc[i][0];
            #pragma unroll
            for (int j = 1; j < 4; j++) mm = fmaxf(mm, sacc[i][j]);
            #pragma unroll
            for (int o = 8; o; o >>= 1) mm = fmaxf(mm, __shfl_xor_sync(0xffffffffu, mm, o));
            float mn = fmaxf(m[i], mm);
            float alpha = expf(m[i] - mn);
            float sum = 0.f;
            #pragma unroll
            for (int j = 0; j < 4; j++) {
                float p = expf(sacc[i][j] - mn);
                pl[i][j] = p; sum += p;
            }
            #pragma unroll
            for (int o = 8; o; o >>= 1) sum += __shfl_xor_sync(0xffffffffu, sum, o);
            l[i] = l[i] * alpha + sum;
            #pragma unroll
            for (int j = 0; j < 4; j++) O[i][j] *= alpha;
            m[i] = mn;
        }

        __syncthreads();
        #pragma unroll
        for (int i = 0; i < 4; i++)
            #pragma unroll
            for (int j = 0; j < 4; j++)
                KP[(4 * ty + i) * 65 + 4 * tx + j] = pl[i][j];
        __syncthreads();

        for (int cc = 0; cc < 64; cc++) {
            float a[4], b[4];
            #pragma unroll
            for (int i = 0; i < 4; i++) a[i] = KP[(4 * ty + i) * 65 + cc];
            #pragma unroll
            for (int j = 0; j < 4; j++) b[j] = Vs[cc * 64 + 4 * tx + j];
            #pragma unroll
            for (int i = 0; i < 4; i++)
                #pragma unroll
                for (int j = 0; j < 4; j++) O[i][j] = fmaf(a[i], b[j], O[i][j]);
        }
    }

    #pragma unroll
    for (int i = 0; i < 4; i++) {
        float inv = 1.f / l[i];
        #pragma unroll
        for (int j = 0; j < 4; j++)
            g_o[(size_t)(q0 + 4 * ty + i) * DIM + h * 64 + 4 * tx + j] = O[i][j] * inv;
    }
}

// ------------------------- router / aux / combine -------------------------
__global__ void __launch_bounds__(256) router_kernel(const float* __restrict__ rw) {
    int t = blockIdx.x;
    int wid = threadIdx.x >> 5, lane = threadIdx.x & 31;
    const float* hr = g_h2 + (size_t)t * DIM;
    const float* wr = rw + (size_t)wid * DIM;
    float s = 0.f;
    for (int i = lane; i < DIM; i += 32) s += hr[i] * wr[i];
    for (int o = 16; o; o >>= 1) s += __shfl_xor_sync(0xffffffffu, s, o);
    __shared__ float lg[NE];
    if (lane == 0) lg[wid] = s;
    __syncthreads();
    if (threadIdx.x == 0) {
        float mx = lg[0];
        #pragma unroll
        for (int e = 1; e < NE; e++) mx = fmaxf(mx, lg[e]);
        float p[NE]; float se = 0.f;
        #pragma unroll
        for (int e = 0; e < NE; e++) { p[e] = expf(lg[e] - mx); se += p[e]; }
        float inv = 1.f / se;
        #pragma unroll
        for (int e = 0; e < NE; e++) { p[e] *= inv; g_probs[t * NE + e] = p[e]; }
        int i0 = 0;
        #pragma unroll
        for (int e = 1; e < NE; e++) if (p[e] > p[i0]) i0 = e;
        int i1 = (i0 == 0) ? 1 : 0;
        #pragma unroll
        for (int e = 0; e < NE; e++) if (e != i0 && p[e] > p[i1]) i1 = e;
        float sw = p[i0] + p[i1];
        g_topw[t * 2 + 0] = p[i0] / sw;
        g_topw[t * 2 + 1] = p[i1] / sw;
        int pos0 = atomicAdd(&g_cnt[i0], 1);
        g_atok[(size_t)i0 * SQ + pos0] = t; g_aslot[(size_t)i0 * SQ + pos0] = 0;
        int pos1 = atomicAdd(&g_cnt[i1], 1);
        g_atok[(size_t)i1 * SQ + pos1] = t; g_aslot[(size_t)i1 * SQ + pos1] = 1;
    }
}

__global__ void __launch_bounds__(256) aux_kernel(float* __restrict__ out, int do_write) {
    int wid = threadIdx.x >> 5, lane = threadIdx.x & 31;
    float s = 0.f;
    for (int t = lane; t < SQ; t += 32) s += g_probs[t * NE + wid];
    for (int o = 16; o; o >>= 1) s += __shfl_xor_sync(0xffffffffu, s, o);
    __shared__ float mp[NE];
    if (lane == 0) mp[wid] = s * (1.f / SQ);
    __syncthreads();
    if (threadIdx.x == 0 && do_write) {
        float a = 0.f;
        #pragma unroll
        for (int e = 0; e < NE; e++) a += mp[e] * mp[e];
        out[(size_t)SQ * DIM] = (float)NE * a;
    }
}

__global__ void __launch_bounds__(256) combine_kernel(float* __restrict__ out) {
    int t = blockIdx.x;
    for (int i = threadIdx.x; i < DIM; i += 256) {
        size_t off = (size_t)t * DIM + i;
        out[off] = g_x2[off] + g_y[((size_t)t * 2) * DIM + i]
                            + g_y[((size_t)t * 2 + 1) * DIM + i];
    }
}

// ------------------------- launch -------------------------
extern "C" void kernel_launch(void* const* d_in, const int* in_sizes, int n_in,
                              void* d_out, int out_size) {
    const float* x        = (const float*)d_in[0];
    const float* qkv_w    = (const float*)d_in[1];
    const float* out_w    = (const float*)d_in[2];
    const float* router_w = (const float*)d_in[3];
    const float* w1       = (const float*)d_in[4];
    const float* w2       = (const float*)d_in[5];
    const float* n1       = (const float*)d_in[6];
    const float* n2       = (const float*)d_in[7];
    float* out = (float*)d_out;

    cudaFuncSetAttribute(attn_kernel, cudaFuncAttributeMaxDynamicSharedMemorySize, 49664);

    zero_cnt_kernel<<<1, 32>>>();
    rmsnorm_kernel<<<SQ, 256>>>(x, n1, 0);
    tc_gemm<0, 1><<<dim3(SQ / 128, 3 * DIM / 128), 512>>>(qkv_w, nullptr, DIM);
    rope_kernel<<<SQ, 256>>>();
    attn_kernel<<<dim3(SQ / 64, NH), 256, 49664>>>();
    tc_gemm<1, 1><<<dim3(SQ / 128, DIM / 128), 512>>>(out_w, x, DIM);
    rmsnorm_kernel<<<SQ, 256>>>(x, n2, 1);
    router_kernel<<<SQ, 256>>>(router_w);
    aux_kernel<<<1, 256>>>(out, out_size > SQ * DIM ? 1 : 0);
    tc_gemm<2, 0><<<dim3(SQ / 128, DFF / 128, NE), 512>>>(w1, nullptr, DIM);
    tc_gemm<3, 0><<<dim3(SQ / 128, DIM / 128, NE), 512>>>(w2, nullptr, DFF);
    combine_kernel<<<SQ, 256>>>(out);
}

// round 7
// speedup vs baseline: 1.0653x; 1.0653x over previous
#include <cuda_runtime.h>
#include <math.h>
#include <stdint.h>

#define SQ   2048
#define DIM  1024
#define NH   16
#define HD   64
#define DFF  4096
#define NE   8
#define EPSV 1.1920928955078125e-07f
#define NEG_INF (__int_as_float(0xff800000))

// ------------------------- scratch (device globals) -------------------------
__device__ float g_h   [(size_t)SQ*DIM];
__device__ float g_qkv [(size_t)SQ*3*DIM];
__device__ float g_o   [(size_t)SQ*DIM];
__device__ float g_x2  [(size_t)SQ*DIM];
__device__ float g_h2  [(size_t)SQ*DIM];
__device__ float g_probs[(size_t)SQ*NE];
__device__ float g_topw [(size_t)SQ*2];
__device__ int   g_cnt  [NE];
__device__ int   g_atok [(size_t)NE*SQ];
__device__ int   g_aslot[(size_t)NE*SQ];
__device__ float g_hid  [(size_t)NE*SQ*DFF];   // 256 MB bss scratch
__device__ float g_y    [(size_t)SQ*2*DIM];

// ------------------------- helpers -------------------------
__device__ __forceinline__ uint32_t f2tf32(float x) {
    uint32_t r;
    asm("cvt.rna.tf32.f32 %0, %1;" : "=r"(r) : "f"(x));
    return r;
}

// float4 accumulator, scalar operands — nothing address-taken, no local memory.
__device__ __forceinline__ void mma4(float4& c,
                                     uint32_t a0, uint32_t a1, uint32_t a2, uint32_t a3,
                                     uint32_t b0, uint32_t b1) {
    asm volatile(
        "mma.sync.aligned.m16n8k8.row.col.f32.tf32.tf32.f32 "
        "{%0,%1,%2,%3}, {%4,%5,%6,%7}, {%8,%9}, {%0,%1,%2,%3};"
        : "+f"(c.x), "+f"(c.y), "+f"(c.z), "+f"(c.w)
        : "r"(a0), "r"(a1), "r"(a2), "r"(a3), "r"(b0), "r"(b1));
}

__device__ __forceinline__ void cp_async16(uint32_t saddr, const void* gptr, int srcsz) {
    asm volatile("cp.async.ca.shared.global [%0], [%1], 16, %2;"
                 :: "r"(saddr), "l"(gptr), "r"(srcsz) : "memory");
}
__device__ __forceinline__ void cp_commit() { asm volatile("cp.async.commit_group;" ::: "memory"); }
__device__ __forceinline__ void cp_wait0()  { asm volatile("cp.async.wait_group 0;" ::: "memory"); }

// ------------------------- small kernels -------------------------
__global__ void zero_cnt_kernel() {
    if (threadIdx.x < NE) g_cnt[threadIdx.x] = 0;
}

__global__ void __launch_bounds__(256) rmsnorm_kernel(const float* __restrict__ xin,
                                                      const float* __restrict__ w, int which) {
    const float* src = which ? g_x2 : xin;
    float* dst = which ? g_h2 : g_h;
    int t = blockIdx.x;
    const float* xr = src + (size_t)t * DIM;
    float s = 0.f;
    for (int i = threadIdx.x; i < DIM; i += 256) { float v = xr[i]; s += v * v; }
    __shared__ float red[8];
    for (int o = 16; o; o >>= 1) s += __shfl_xor_sync(0xffffffffu, s, o);
    if ((threadIdx.x & 31) == 0) red[threadIdx.x >> 5] = s;
    __syncthreads();
    if (threadIdx.x == 0) {
        float v = 0.f;
        #pragma unroll
        for (int i = 0; i < 8; i++) v += red[i];
        red[0] = v;
    }
    __syncthreads();
    float rs = rsqrtf(red[0] * (1.f / DIM) + EPSV);
    float* dr = dst + (size_t)t * DIM;
    for (int i = threadIdx.x; i < DIM; i += 256) dr[i] = xr[i] * rs * w[i];
}

__global__ void __launch_bounds__(256) rope_kernel() {
    int t = blockIdx.x;
    for (int it = threadIdx.x; it < 1024; it += 256) {
        int which = it >> 9;
        int rem = it & 511;
        int hh = rem >> 5, j = rem & 31;
        float inv = expf(-0.28782313662425575f * (float)j);
        float ang = (float)t * inv;
        float sn, cs;
        sincosf(ang, &sn, &cs);
        float* p = g_qkv + (size_t)t * 3072 + which * 1024 + hh * 64;
        float x1 = p[j], x2 = p[j + 32];
        p[j]      = x1 * cs - x2 * sn;
        p[j + 32] = x2 * cs + x1 * sn;
    }
}

// ------------------------- tf32 tensor-core GEMM -------------------------
#define BROW 20

#define LOADB(J) \
    float fb##J##0 = bs[(wn * 32 + 8 * J + g) * BROW + kk + t]; \
    float fb##J##1 = bs[(wn * 32 + 8 * J + g) * BROW + kk + t + 4];

#define CVTB(J) \
    uint32_t hb##J##0 = f2tf32(fb##J##0); \
    uint32_t hb##J##1 = f2tf32(fb##J##1);

#define SPLB(J) \
    uint32_t hb##J##0 = f2tf32(fb##J##0); \
    uint32_t lb##J##0 = f2tf32(fb##J##0 - __uint_as_float(hb##J##0)); \
    uint32_t hb##J##1 = f2tf32(fb##J##1); \
    uint32_t lb##J##1 = f2tf32(fb##J##1 - __uint_as_float(hb##J##1));

#define DOROW(TI) { \
    int rb = (wm * 32 + TI * 16 + g) * BROW + kk + t; \
    uint32_t ha0 = f2tf32(as[rb]); \
    uint32_t ha1 = f2tf32(as[rb + 8 * BROW]); \
    uint32_t ha2 = f2tf32(as[rb + 4]); \
    uint32_t ha3 = f2tf32(as[rb + 8 * BROW + 4]); \
    mma4(c##TI##0, ha0, ha1, ha2, ha3, hb00, hb01); \
    mma4(c##TI##1, ha0, ha1, ha2, ha3, hb10, hb11); \
    mma4(c##TI##2, ha0, ha1, ha2, ha3, hb20, hb21); \
    mma4(c##TI##3, ha0, ha1, ha2, ha3, hb30, hb31); }

#define DOROW_P(TI) { \
    int rb = (wm * 32 + TI * 16 + g) * BROW + kk + t; \
    float fa0 = as[rb]; \
    float fa1 = as[rb + 8 * BROW]; \
    float fa2 = as[rb + 4]; \
    float fa3 = as[rb + 8 * BROW + 4]; \
    uint32_t ha0 = f2tf32(fa0), ha1 = f2tf32(fa1), ha2 = f2tf32(fa2), ha3 = f2tf32(fa3); \
    uint32_t la0 = f2tf32(fa0 - __uint_as_float(ha0)); \
    uint32_t la1 = f2tf32(fa1 - __uint_as_float(ha1)); \
    uint32_t la2 = f2tf32(fa2 - __uint_as_float(ha2)); \
    uint32_t la3 = f2tf32(fa3 - __uint_as_float(ha3)); \
    mma4(c##TI##0, la0, la1, la2, la3, hb00, hb01); \
    mma4(c##TI##0, ha0, ha1, ha2, ha3, lb00, lb01); \
    mma4(c##TI##0, ha0, ha1, ha2, ha3, hb00, hb01); \
    mma4(c##TI##1, la0, la1, la2, la3, hb10, hb11); \
    mma4(c##TI##1, ha0, ha1, ha2, ha3, lb10, lb11); \
    mma4(c##TI##1, ha0, ha1, ha2, ha3, hb10, hb11); \
    mma4(c##TI##2, la0, la1, la2, la3, hb20, hb21); \
    mma4(c##TI##2, ha0, ha1, ha2, ha3, lb20, lb21); \
    mma4(c##TI##2, ha0, ha1, ha2, ha3, hb20, hb21); \
    mma4(c##TI##3, la0, la1, la2, la3, hb30, hb31); \
    mma4(c##TI##3, ha0, ha1, ha2, ha3, lb30, lb31); \
    mma4(c##TI##3, ha0, ha1, ha2, ha3, hb30, hb31); }

#define EPI1(CT, J) do { \
    int col = n0 + wn * 32 + 8 * J + 2 * t; \
    float v0 = rh ? (CT).z : (CT).x; \
    float v1 = rh ? (CT).w : (CT).y; \
    if (MODE == 0) { \
        *(float2*)(g_qkv + (size_t)r * 3072 + col) = make_float2(v0, v1); \
    } else if (MODE == 1) { \
        size_t off = (size_t)r * DIM + col; \
        g_x2[off]     = xres[off]     + v0; \
        g_x2[off + 1] = xres[off + 1] + v1; \
    } else if (MODE == 2) { \
        float gl0 = 0.5f * v0 * (1.f + erff(v0 * 0.7071067811865476f)); \
        float gl1 = 0.5f * v1 * (1.f + erff(v1 * 0.7071067811865476f)); \
        *(float2*)(g_hid + (size_t)e * SQ * DFF + (size_t)r * DFF + col) = make_float2(gl0, gl1); \
    } else { \
        *(float2*)(g_y + ((size_t)tok * 2 + slot) * DIM + col) = make_float2(v0 * wt, v1 * wt); \
    } \
} while (0)

template<int MODE, int PREC>
__global__ void __launch_bounds__(512) tc_gemm(const float* __restrict__ W,
                                               const float* __restrict__ xres,
                                               int Kdim) {
    __shared__ float As[2][128 * BROW];
    __shared__ float Bs[2][128 * BROW];

    int m0 = blockIdx.x * 128, n0 = blockIdx.y * 128;
    int e = (MODE >= 2) ? blockIdx.z : 0;
    int Mv = (MODE >= 2) ? g_cnt[e] : SQ;
    if (MODE >= 2 && m0 >= Mv) return;

    const float* A;
    const float* B;
    if (MODE == 0)      { A = g_h;                          B = W; }
    else if (MODE == 1) { A = g_o;                          B = W; }
    else if (MODE == 2) { A = g_h2;                         B = W + (size_t)e * DFF * DIM; }
    else                { A = g_hid + (size_t)e * SQ * DFF; B = W + (size_t)e * DIM * DFF; }

    int tid = threadIdx.x;
    int lr = tid >> 2, kq = tid & 3;

    const float* arow;
    int apred = 16;
    if (MODE == 2) {
        int r = m0 + lr;
        bool valid = r < Mv;
        apred = valid ? 16 : 0;
        int row = valid ? g_atok[(size_t)e * SQ + r] : 0;
        arow = A + (size_t)row * Kdim + kq * 4;
    } else {
        arow = A + (size_t)(m0 + lr) * Kdim + kq * 4;
    }
    const float* brow = B + (size_t)(n0 + lr) * Kdim + kq * 4;

    uint32_t a_s = (uint32_t)__cvta_generic_to_shared(&As[0][lr * BROW + kq * 4]);
    uint32_t b_s = (uint32_t)__cvta_generic_to_shared(&Bs[0][lr * BROW + kq * 4]);
    const uint32_t bufoff = 128 * BROW * 4;

#define LOADG(BUF, K0)                                            \
    do {                                                          \
        cp_async16(a_s + (BUF) * bufoff, arow + (K0), apred);     \
        cp_async16(b_s + (BUF) * bufoff, brow + (K0), 16);        \
        cp_commit();                                              \
    } while (0)

    int warp = tid >> 5, lane = tid & 31;
    int wm = warp >> 2, wn = warp & 3;
    int g = lane >> 2, t = lane & 3;

    float4 c00 = make_float4(0.f, 0.f, 0.f, 0.f);
    float4 c01 = c00, c02 = c00, c03 = c00;
    float4 c10 = c00, c11 = c00, c12 = c00, c13 = c00;

    int nIter = Kdim >> 4;
    LOADG(0, 0);

    for (int it = 0; it < nIter; ++it) {
        cp_wait0();
        __syncthreads();
        int nxt = it + 1;
        if (nxt < nIter) LOADG(nxt & 1, nxt << 4);

        const float* as = As[it & 1];
        const float* bs = Bs[it & 1];
        #pragma unroll
        for (int kh = 0; kh < 2; kh++) {
            int kk = kh * 8;
            LOADB(0) LOADB(1) LOADB(2) LOADB(3)
            if (PREC) {
                SPLB(0) SPLB(1) SPLB(2) SPLB(3)
                DOROW_P(0)
                DOROW_P(1)
            } else {
                CVTB(0) CVTB(1) CVTB(2) CVTB(3)
                DOROW(0)
                DOROW(1)
            }
        }
        __syncthreads();
    }

    // ---------------- epilogue ----------------
    for (int rh = 0; rh < 2; rh++) {
        {
            int r = m0 + wm * 32 + g + rh * 8;
            if (!(MODE >= 2 && r >= Mv)) {
                int tok = 0, slot = 0; float wt = 0.f;
                if (MODE == 3) {
                    tok  = g_atok [(size_t)e * SQ + r];
                    slot = g_aslot[(size_t)e * SQ + r];
                    wt   = g_topw[tok * 2 + slot];
                }
                EPI1(c00, 0); EPI1(c01, 1); EPI1(c02, 2); EPI1(c03, 3);
            }
        }
        {
            int r = m0 + wm * 32 + 16 + g + rh * 8;
            if (!(MODE >= 2 && r >= Mv)) {
                int tok = 0, slot = 0; float wt = 0.f;
                if (MODE == 3) {
                    tok  = g_atok [(size_t)e * SQ + r];
                    slot = g_aslot[(size_t)e * SQ + r];
                    wt   = g_topw[tok * 2 + slot];
                }
                EPI1(c10, 0); EPI1(c11, 1); EPI1(c12, 2); EPI1(c13, 3);
            }
        }
    }
#undef LOADG
}

// ------------------------- attention (flash, 3xTF32 tensor cores) -------------------------
// 128 threads = 4 warps; warp handles 16 q-rows. Br=Bc=64, D=64.
// Smem tiles stride 68 floats: bank = (4n + t) mod 32 bijective -> conflict-free LDS.
// Q/K/P/V all hi/lo split (3 MMAs) => near-fp32 accuracy (router-flip safe).
#define ASTRIDE 68

// 3xTF32 MMA vs B loaded from array BASE at row (8*J+g), k = ks (+4)
#define ATT_MMA3(ACC, J, BASE) { \
    float fb0 = BASE[(8 * (J) + g) * ASTRIDE + ks]; \
    float fb1 = BASE[(8 * (J) + g) * ASTRIDE + ks + 4]; \
    uint32_t hb0 = f2tf32(fb0), hb1 = f2tf32(fb1); \
    uint32_t lb0 = f2tf32(fb0 - __uint_as_float(hb0)); \
    uint32_t lb1 = f2tf32(fb1 - __uint_as_float(hb1)); \
    mma4(ACC, la0, la1, la2, la3, hb0, hb1); \
    mma4(ACC, ha0, ha1, ha2, ha3, lb0, lb1); \
    mma4(ACC, ha0, ha1, ha2, ha3, hb0, hb1); }

#define ATT_ALOAD(BASE) \
    float fa0 = BASE[qb0 + ks], fa1 = BASE[qb1 + ks]; \
    float fa2 = BASE[qb0 + ks + 4], fa3 = BASE[qb1 + ks + 4]; \
    uint32_t ha0 = f2tf32(fa0), ha1 = f2tf32(fa1), ha2 = f2tf32(fa2), ha3 = f2tf32(fa3); \
    uint32_t la0 = f2tf32(fa0 - __uint_as_float(ha0)); \
    uint32_t la1 = f2tf32(fa1 - __uint_as_float(ha1)); \
    uint32_t la2 = f2tf32(fa2 - __uint_as_float(ha2)); \
    uint32_t la3 = f2tf32(fa3 - __uint_as_float(ha3));

#define ATT_MASK(J) { \
    int c0 = 8 * (J) + 2 * t; \
    if (c0     > r0l) s##J.x = NEG_INF; \
    if (c0 + 1 > r0l) s##J.y = NEG_INF; \
    if (c0     > r1l) s##J.z = NEG_INF; \
    if (c0 + 1 > r1l) s##J.w = NEG_INF; }

#define ATT_MX(J) \
    mx0 = fmaxf(mx0, fmaxf(s##J.x, s##J.y)); \
    mx1 = fmaxf(mx1, fmaxf(s##J.z, s##J.w));

#define ATT_EXP(J) \
    s##J.x = __expf(s##J.x - mn0); s##J.y = __expf(s##J.y - mn0); \
    s##J.z = __expf(s##J.z - mn1); s##J.w = __expf(s##J.w - mn1); \
    sum0 += s##J.x + s##J.y; sum1 += s##J.z + s##J.w;

#define ATT_SCL(J) \
    o##J.x *= al0; o##J.y *= al0; o##J.z *= al1; o##J.w *= al1;

#define ATT_PST(J) { \
    int c0 = 8 * (J) + 2 * t; \
    Ps[qb0 + c0] = s##J.x; Ps[qb0 + c0 + 1] = s##J.y; \
    Ps[qb1 + c0] = s##J.z; Ps[qb1 + c0 + 1] = s##J.w; }

#define ATT_OST(J) { \
    int c0 = 8 * (J) + 2 * t; \
    float* p0 = g_o + (size_t)(q0 + r0l) * DIM + h * 64 + c0; \
    float* p1 = g_o + (size_t)(q0 + r1l) * DIM + h * 64 + c0; \
    p0[0] = o##J.x * inv0; p0[1] = o##J.y * inv0; \
    p1[0] = o##J.z * inv1; p1[1] = o##J.w * inv1; }

__global__ void __launch_bounds__(128) attn_tc_kernel() {
    extern __shared__ float sma[];
    float* Qs = sma;                 // [64][68]  scaled by 1/8
    float* Ks = sma + 64 * ASTRIDE;  // [64][68]  [key][d]
    float* Vt = sma + 2 * 64 * ASTRIDE; // [64][68]  [d][key]  (transposed)
    float* Ps = sma + 3 * 64 * ASTRIDE; // [64][68]

    int h  = blockIdx.y;
    int qt = (int)gridDim.x - 1 - (int)blockIdx.x;  // biggest tiles launch first
    int q0 = qt * 64;
    int tid = threadIdx.x, wr = tid >> 5, lane = tid & 31;
    int g = lane >> 2, t = lane & 3;
    int r0l = wr * 16 + g, r1l = r0l + 8;
    int qb0 = r0l * ASTRIDE, qb1 = r1l * ASTRIDE;

    for (int idx = tid; idx < 64 * 16; idx += 128) {
        int r = idx >> 4, d4 = idx & 15;
        float4 v = *(const float4*)(g_qkv + (size_t)(q0 + r) * 3072 + h * 64 + d4 * 4);
        float* q = Qs + r * ASTRIDE + d4 * 4;
        q[0] = v.x * 0.125f; q[1] = v.y * 0.125f; q[2] = v.z * 0.125f; q[3] = v.w * 0.125f;
    }

    float4 o0 = make_float4(0.f, 0.f, 0.f, 0.f);
    float4 o1 = o0, o2 = o0, o3 = o0, o4 = o0, o5 = o0, o6 = o0, o7 = o0;
    float m0 = NEG_INF, m1 = NEG_INF, l0 = 0.f, l1 = 0.f;

    for (int kt = 0; kt <= qt; kt++) {
        int k0 = kt * 64;
        __syncthreads();   // prior iteration done with Ks/Vt/Ps (and Q visible on iter 0)
        for (int idx = tid; idx < 64 * 16; idx += 128) {
            int r = idx >> 4, d4 = idx & 15;
            const float* kb = g_qkv + (size_t)(k0 + r) * 3072 + 1024 + h * 64 + d4 * 4;
            float4 kv = *(const float4*)kb;
            float* kp = Ks + r * ASTRIDE + d4 * 4;
            kp[0] = kv.x; kp[1] = kv.y; kp[2] = kv.z; kp[3] = kv.w;
            float4 vv = *(const float4*)(kb + 1024);
            Vt[(d4 * 4 + 0) * ASTRIDE + r] = vv.x;
            Vt[(d4 * 4 + 1) * ASTRIDE + r] = vv.y;
            Vt[(d4 * 4 + 2) * ASTRIDE + r] = vv.z;
            Vt[(d4 * 4 + 3) * ASTRIDE + r] = vv.w;
        }
        __syncthreads();

        // ---- S = Q @ K^T (3xTF32) ----
        float4 s0 = make_float4(0.f, 0.f, 0.f, 0.f);
        float4 s1 = s0, s2 = s0, s3 = s0, s4 = s0, s5 = s0, s6 = s0, s7 = s0;
        #pragma unroll
        for (int ss = 0; ss < 8; ss++) {
            int ks = t + 8 * ss;
            ATT_ALOAD(Qs)
            ATT_MMA3(s0, 0, Ks) ATT_MMA3(s1, 1, Ks) ATT_MMA3(s2, 2, Ks) ATT_MMA3(s3, 3, Ks)
            ATT_MMA3(s4, 4, Ks) ATT_MMA3(s5, 5, Ks) ATT_MMA3(s6, 6, Ks) ATT_MMA3(s7, 7, Ks)
        }
        if (kt == qt) {
            ATT_MASK(0) ATT_MASK(1) ATT_MASK(2) ATT_MASK(3)
            ATT_MASK(4) ATT_MASK(5) ATT_MASK(6) ATT_MASK(7)
        }

        // ---- online softmax ----
        float mx0 = NEG_INF, mx1 = NEG_INF;
        ATT_MX(0) ATT_MX(1) ATT_MX(2) ATT_MX(3) ATT_MX(4) ATT_MX(5) ATT_MX(6) ATT_MX(7)
        mx0 = fmaxf(mx0, __shfl_xor_sync(0xffffffffu, mx0, 1));
        mx0 = fmaxf(mx0, __shfl_xor_sync(0xffffffffu, mx0, 2));
        mx1 = fmaxf(mx1, __shfl_xor_sync(0xffffffffu, mx1, 1));
        mx1 = fmaxf(mx1, __shfl_xor_sync(0xffffffffu, mx1, 2));
        float mn0 = fmaxf(m0, mx0), mn1 = fmaxf(m1, mx1);
        float al0 = __expf(m0 - mn0), al1 = __expf(m1 - mn1);
        float sum0 = 0.f, sum1 = 0.f;
        ATT_EXP(0) ATT_EXP(1) ATT_EXP(2) ATT_EXP(3) ATT_EXP(4) ATT_EXP(5) ATT_EXP(6) ATT_EXP(7)
        sum0 += __shfl_xor_sync(0xffffffffu, sum0, 1);
        sum0 += __shfl_xor_sync(0xffffffffu, sum0, 2);
        sum1 += __shfl_xor_sync(0xffffffffu, sum1, 1);
        sum1 += __shfl_xor_sync(0xffffffffu, sum1, 2);
        l0 = l0 * al0 + sum0; l1 = l1 * al1 + sum1;
        m0 = mn0; m1 = mn1;
        ATT_SCL(0) ATT_SCL(1) ATT_SCL(2) ATT_SCL(3) ATT_SCL(4) ATT_SCL(5) ATT_SCL(6) ATT_SCL(7)

        // ---- write P, then O += P @ V (3xTF32) ----
        ATT_PST(0) ATT_PST(1) ATT_PST(2) ATT_PST(3) ATT_PST(4) ATT_PST(5) ATT_PST(6) ATT_PST(7)
        __syncthreads();
        #pragma unroll
        for (int ss = 0; ss < 8; ss++) {
            int ks = t + 8 * ss;
            ATT_ALOAD(Ps)
            ATT_MMA3(o0, 0, Vt) ATT_MMA3(o1, 1, Vt) ATT_MMA3(o2, 2, Vt) ATT_MMA3(o3, 3, Vt)
            ATT_MMA3(o4, 4, Vt) ATT_MMA3(o5, 5, Vt) ATT_MMA3(o6, 6, Vt) ATT_MMA3(o7, 7, Vt)
        }
    }

    float inv0 = 1.f / l0, inv1 = 1.f / l1;
    ATT_OST(0) ATT_OST(1) ATT_OST(2) ATT_OST(3) ATT_OST(4) ATT_OST(5) ATT_OST(6) ATT_OST(7)
}

// ------------------------- router / aux / combine -------------------------
__global__ void __launch_bounds__(256) router_kernel(const float* __restrict__ rw) {
    int t = blockIdx.x;
    int wid = threadIdx.x >> 5, lane = threadIdx.x & 31;
    const float* hr = g_h2 + (size_t)t * DIM;
    const float* wr = rw + (size_t)wid * DIM;
    float s = 0.f;
    for (int i = lane; i < DIM; i += 32) s += hr[i] * wr[i];
    for (int o = 16; o; o >>= 1) s += __shfl_xor_sync(0xffffffffu, s, o);
    __shared__ float lg[NE];
    if (lane == 0) lg[wid] = s;
    __syncthreads();
    if (threadIdx.x == 0) {
        float mx = lg[0];
        #pragma unroll
        for (int e = 1; e < NE; e++) mx = fmaxf(mx, lg[e]);
        float p[NE]; float se = 0.f;
        #pragma unroll
        for (int e = 0; e < NE; e++) { p[e] = expf(lg[e] - mx); se += p[e]; }
        float inv = 1.f / se;
        #pragma unroll
        for (int e = 0; e < NE; e++) { p[e] *= inv; g_probs[t * NE + e] = p[e]; }
        int i0 = 0;
        #pragma unroll
        for (int e = 1; e < NE; e++) if (p[e] > p[i0]) i0 = e;
        int i1 = (i0 == 0) ? 1 : 0;
        #pragma unroll
        for (int e = 0; e < NE; e++) if (e != i0 && p[e] > p[i1]) i1 = e;
        float sw = p[i0] + p[i1];
        g_topw[t * 2 + 0] = p[i0] / sw;
        g_topw[t * 2 + 1] = p[i1] / sw;
        int pos0 = atomicAdd(&g_cnt[i0], 1);
        g_atok[(size_t)i0 * SQ + pos0] = t; g_aslot[(size_t)i0 * SQ + pos0] = 0;
        int pos1 = atomicAdd(&g_cnt[i1], 1);
        g_atok[(size_t)i1 * SQ + pos1] = t; g_aslot[(size_t)i1 * SQ + pos1] = 1;
    }
}

__global__ void __launch_bounds__(256) aux_kernel(float* __restrict__ out, int do_write) {
    int wid = threadIdx.x >> 5, lane = threadIdx.x & 31;
    float s = 0.f;
    for (int t = lane; t < SQ; t += 32) s += g_probs[t * NE + wid];
    for (int o = 16; o; o >>= 1) s += __shfl_xor_sync(0xffffffffu, s, o);
    __shared__ float mp[NE];
    if (lane == 0) mp[wid] = s * (1.f / SQ);
    __syncthreads();
    if (threadIdx.x == 0 && do_write) {
        float a = 0.f;
        #pragma unroll
        for (int e = 0; e < NE; e++) a += mp[e] * mp[e];
        out[(size_t)SQ * DIM] = (float)NE * a;
    }
}

__global__ void __launch_bounds__(256) combine_kernel(float* __restrict__ out) {
    int t = blockIdx.x;
    for (int i = threadIdx.x; i < DIM; i += 256) {
        size_t off = (size_t)t * DIM + i;
        out[off] = g_x2[off] + g_y[((size_t)t * 2) * DIM + i]
                            + g_y[((size_t)t * 2 + 1) * DIM + i];
    }
}

// ------------------------- launch -------------------------
extern "C" void kernel_launch(void* const* d_in, const int* in_sizes, int n_in,
                              void* d_out, int out_size) {
    const float* x        = (const float*)d_in[0];
    const float* qkv_w    = (const float*)d_in[1];
    const float* out_w    = (const float*)d_in[2];
    const float* router_w = (const float*)d_in[3];
    const float* w1       = (const float*)d_in[4];
    const float* w2       = (const float*)d_in[5];
    const float* n1       = (const float*)d_in[6];
    const float* n2       = (const float*)d_in[7];
    float* out = (float*)d_out;

    const int attn_smem = 4 * 64 * ASTRIDE * 4;  // 69632 B
    cudaFuncSetAttribute(attn_tc_kernel, cudaFuncAttributeMaxDynamicSharedMemorySize, attn_smem);

    zero_cnt_kernel<<<1, 32>>>();
    rmsnorm_kernel<<<SQ, 256>>>(x, n1, 0);
    tc_gemm<0, 1><<<dim3(SQ / 128, 3 * DIM / 128), 512>>>(qkv_w, nullptr, DIM);
    rope_kernel<<<SQ, 256>>>();
    attn_tc_kernel<<<dim3(SQ / 64, NH), 128, attn_smem>>>();
    tc_gemm<1, 1><<<dim3(SQ / 128, DIM / 128), 512>>>(out_w, x, DIM);
    rmsnorm_kernel<<<SQ, 256>>>(x, n2, 1);
    router_kernel<<<SQ, 256>>>(router_w);
    aux_kernel<<<1, 256>>>(out, out_size > SQ * DIM ? 1 : 0);
    tc_gemm<2, 0><<<dim3(SQ / 128, DFF / 128, NE), 512>>>(w1, nullptr, DIM);
    tc_gemm<3, 0><<<dim3(SQ / 128, DIM / 128, NE), 512>>>(w2, nullptr, DFF);
    combine_kernel<<<SQ, 256>>>(out);
}